// round 4
// baseline (speedup 1.0000x reference)
#include <cuda_runtime.h>
#include <stdint.h>

#define N_OBJ 16384
#define N_DIM 4096
#define LUTN  16384
#define INV_SQRT2 0.70710678118654752440f

// 134 MB scratch: bin index per (dim, object), transposed layout [dim][object].
__device__ uint16_t g_bins[(size_t)N_DIM * N_OBJ];
__device__ float    g_zthr[N_OBJ];        // zthr[j] = max f32 z with p(z) <= thr(j)
__device__ uint16_t g_lut[LUTN + 1];      // z-bucket -> lower-bound bin

__device__ __forceinline__ float thr(int j) {
    return __fmul_rn(0.05f, (float)(j + 1) * 6.103515625e-05f);
}
__device__ __forceinline__ float pz(float z) {
    return 0.5f * (1.0f + erff(z));
}

// ---------------- init 1: z-space thresholds (bit-level binary search) ----
__global__ void init_zthr_kernel() {
    int j = blockIdx.x * 256 + threadIdx.x;
    if (j >= N_OBJ) return;
    float t = thr(j);
    unsigned lo = __float_as_uint(1e-10f);       // p(-tiny) ~ 0.5 > t
    unsigned hi = __float_as_uint(12.0f);        // p(-12) = 0 <= t
    while (lo < hi) {
        unsigned mid = (lo + hi) >> 1;
        if (pz(-__uint_as_float(mid)) <= t) hi = mid; else lo = mid + 1;
    }
    g_zthr[j] = -__uint_as_float(lo);
}

// ---------------- init 2: bucket LUT over [zthr[0], zthr[N-1]] ------------
__global__ void init_lut_kernel() {
    int k = blockIdx.x * 256 + threadIdx.x;
    if (k > LUTN) return;
    float zlo = g_zthr[0], zhi = g_zthr[N_OBJ - 1];
    float zk = zlo + (zhi - zlo) * ((float)k / (float)LUTN);
    int lo = 0, hi = N_OBJ - 1;                   // min j with zthr[j] >= zk
    while (lo < hi) {
        int mid = (lo + hi) >> 1;
        if (g_zthr[mid] >= zk) hi = mid; else lo = mid + 1;
    }
    g_lut[k] = (uint16_t)lo;
}

// ---------------- phase 1 -------------------------------------------------
// Block = 512 threads (tx=32 dims, ty=16 objs), tile = 32 dims x 64 objs,
// 4 elements/thread. 64 regs/thread budget (no spills). Division-free:
// predicate fmaf(zthr[j], v, -a) >= 0 is an exact, monotone comparison.
#define P1_THREADS 512
#define DTILES (N_DIM / 32)      // 128
#define OTILES (N_OBJ / 64)      // 256
#define NTILES (DTILES * OTILES) // 32768
#define P1_ZOFF 0
#define P1_LOFF 65536
#define P1_TOFF 98432            // 65536 + 2*(LUTN+1)=32770, padded
#define P1_SMEM (P1_TOFF + 32 * 66 * 2)

__global__ __launch_bounds__(P1_THREADS, 2) void phase1_kernel(
        const float* __restrict__ q_mu, const float* __restrict__ q_var) {
    extern __shared__ char sm[];
    float*    s_zthr = (float*)(sm + P1_ZOFF);
    uint16_t* s_lut  = (uint16_t*)(sm + P1_LOFF);
    uint16_t* s_tile = (uint16_t*)(sm + P1_TOFF);   // [32][66]

    const int tid = threadIdx.x, tx = tid & 31, ty = tid >> 5;
    for (int k = tid; k < N_OBJ; k += P1_THREADS) s_zthr[k] = g_zthr[k];
    for (int k = tid; k <= LUTN; k += P1_THREADS) s_lut[k] = g_lut[k];
    __syncthreads();

    const float zlo = s_zthr[0], zhi = s_zthr[N_OBJ - 1];
    const float invw = (float)LUTN / (zhi - zlo);
    uint32_t* bins32 = reinterpret_cast<uint32_t*>(g_bins);

    for (int t = blockIdx.x; t < NTILES; t += gridDim.x) {
        const int dt = t & (DTILES - 1);
        const int ot = t >> 7;
        const int d = dt * 32 + tx;
        const size_t base = (size_t)(ot * 64 + ty) * N_DIM + d;

        float aa[4], vv[4];
        #pragma unroll
        for (int r = 0; r < 4; r++) {
            float m = q_mu[base + (size_t)(r * 16) * N_DIM];
            vv[r] = q_var[base + (size_t)(r * 16) * N_DIM];
            aa[r] = m * (-INV_SQRT2);            // compare target a = -mu*c
        }

        int lo4[4], hi4[4];
        uint16_t bin4[4];
        #pragma unroll
        for (int r = 0; r < 4; r++) {
            float a = aa[r], v = vv[r];
            // z <= zhi  <=>  zhi*v >= a   (exact via FMA sign)
            bool in_alpha = (fmaf(zhi, v, -a) >= 0.0f);
            bool is_bin0  = (fmaf(zlo, v, -a) >= 0.0f);
            bool mid = in_alpha && !is_bin0;
            int lo = 0, hi = 0;
            if (mid) {
                float zr = __fdividef(a, v);      // approx z, bucket only
                int k = (int)((zr - zlo) * invw);
                k = min(max(k, 1), LUTN - 2);
                lo = s_lut[k - 1];
                hi = s_lut[k + 2];
            }
            lo4[r] = lo; hi4[r] = hi;
            bin4[r] = in_alpha ? (uint16_t)0 : (uint16_t)0xFFFFu;
        }

        // 6 branchless predicated bisection steps, 4 independent chains
        #pragma unroll
        for (int it = 0; it < 6; ++it) {
            #pragma unroll
            for (int r = 0; r < 4; r++) {
                int lo = lo4[r], hi = hi4[r];
                if (lo < hi) {
                    int m = (lo + hi) >> 1;
                    float tz = s_zthr[m];
                    if (fmaf(tz, vv[r], -aa[r]) >= 0.0f) hi4[r] = m;
                    else lo4[r] = m + 1;
                }
            }
        }
        #pragma unroll
        for (int r = 0; r < 4; r++) {
            int lo = lo4[r], hi = hi4[r];
            while (lo < hi) {                     // safety (almost never runs)
                int m = (lo + hi) >> 1;
                if (fmaf(s_zthr[m], vv[r], -aa[r]) >= 0.0f) hi = m;
                else lo = m + 1;
            }
            if (bin4[r] == 0) bin4[r] = (uint16_t)lo;   // mid: lo; bin0: lo==0
            s_tile[tx * 66 + (ty + r * 16)] = bin4[r];
        }
        __syncthreads();
        // transposed coalesced store: 32 dims x 64 objs = 1024 u32
        #pragma unroll
        for (int q = 0; q < 2; q++) {
            int s = q * 512 + tid;
            int dd = s >> 5, pp = s & 31;
            uint32_t val = *(const uint32_t*)&s_tile[dd * 66 + 2 * pp];
            bins32[(size_t)(dt * 32 + dd) * (N_OBJ / 2) + ot * 32 + pp] = val;
        }
        __syncthreads();
    }
}

// ---------------- phase 2: per-dim histogram + bounded scan ---------------
__global__ __launch_bounds__(1024, 2) void phase2_kernel(float* __restrict__ out) {
    extern __shared__ uint32_t hist[];       // up to 16384 u32 = 64 KB
    __shared__ uint32_t s_wsum[32];
    __shared__ uint32_t s_C;
    __shared__ uint32_t red_cnt[32];
    __shared__ int      red_min[32];

    const int tid = threadIdx.x, lane = tid & 31, wid = tid >> 5;
    const int d = blockIdx.x;

    const uint4* row = (const uint4*)(g_bins + (size_t)d * N_OBJ);
    uint4 ra = row[tid];
    uint4 rb = row[tid + 1024];
    uint32_t w[8] = {ra.x, ra.y, ra.z, ra.w, rb.x, rb.y, rb.z, rb.w};

    // C = #(non-sentinel)
    uint32_t cnt = 0;
    #pragma unroll
    for (int q = 0; q < 8; q++) {
        cnt += ((w[q] & 0xFFFFu) != 0xFFFFu);
        cnt += ((w[q] >> 16)     != 0xFFFFu);
    }
    #pragma unroll
    for (int o = 16; o > 0; o >>= 1) cnt += __shfl_down_sync(0xffffffffu, cnt, o);
    if (tid == 0) s_C = 0;
    __syncthreads();
    if (lane == 0 && cnt) atomicAdd(&s_C, cnt);
    __syncthreads();

    const uint32_t C = s_C;
    const int chunks = min(16, (int)((C + 1023u) >> 10));
    if (chunks == 0) { if (tid == 0) out[d] = 0.0f; return; }
    const uint32_t limit = (uint32_t)chunks << 10;

    {   // vectorized zero of hist[0..limit)
        uint4* h4 = (uint4*)hist;
        uint4 z4 = {0u, 0u, 0u, 0u};
        for (int k = tid; k < (int)(limit >> 2); k += 1024) h4[k] = z4;
    }
    __syncthreads();

    // histogram with warp-aggregated (match_any) atomics
    #pragma unroll
    for (int q = 0; q < 16; q++) {
        uint32_t b = (q < 8) ? (w[q] & 0xFFFFu) : (w[q - 8] >> 16);
        bool val = (b < limit);
        uint32_t key = val ? b : 0xFFFFFFFFu;
        unsigned msk = __match_any_sync(0xffffffffu, key);
        int leader = __ffs(msk) - 1;
        if (val && lane == leader) atomicAdd(&hist[b], (uint32_t)__popc(msk));
    }
    __syncthreads();

    // scan: thread t owns bins [t*chunks, (t+1)*chunks), contiguous
    const int bbase = tid * chunks;
    uint32_t s = 0;
    for (int c = 0; c < chunks; ++c) s += hist[bbase + c];

    uint32_t x = s;
    #pragma unroll
    for (int o = 1; o < 32; o <<= 1) {
        uint32_t y = __shfl_up_sync(0xffffffffu, x, o);
        if (lane >= o) x += y;
    }
    if (lane == 31) s_wsum[wid] = x;
    __syncthreads();
    if (wid == 0) {
        uint32_t ww = s_wsum[lane];
        #pragma unroll
        for (int o = 1; o < 32; o <<= 1) {
            uint32_t y = __shfl_up_sync(0xffffffffu, ww, o);
            if (lane >= o) ww += y;
        }
        s_wsum[lane] = ww;
    }
    __syncthreads();
    uint32_t run = x - s + (wid > 0 ? s_wsum[wid - 1] : 0u);

    uint32_t count = 0;
    int firstj = 0x7fffffff;
    for (int c = 0; c < chunks; ++c) {
        int j = bbase + c;
        run += hist[j];
        if (run >= (uint32_t)(j + 1)) { count++; firstj = min(firstj, j); }
    }

    #pragma unroll
    for (int o = 16; o > 0; o >>= 1) {
        count += __shfl_down_sync(0xffffffffu, count, o);
        firstj = min(firstj, __shfl_down_sync(0xffffffffu, firstj, o));
    }
    if (lane == 0) { red_cnt[wid] = count; red_min[wid] = firstj; }
    __syncthreads();
    if (wid == 0) {
        uint32_t cc = red_cnt[lane];
        int mm = red_min[lane];
        #pragma unroll
        for (int o = 16; o > 0; o >>= 1) {
            cc += __shfl_down_sync(0xffffffffu, cc, o);
            mm = min(mm, __shfl_down_sync(0xffffffffu, mm, o));
        }
        if (lane == 0) {
            uint32_t imp = cc + ((mm == 0x7fffffff) ? 0u : (uint32_t)mm);
            out[d] = (float)imp;
        }
    }
}

extern "C" void kernel_launch(void* const* d_in, const int* in_sizes, int n_in,
                              void* d_out, int out_size) {
    const float* q_mu  = (const float*)d_in[0];
    const float* q_var = (const float*)d_in[1];
    float* out = (float*)d_out;

    cudaFuncSetAttribute((const void*)phase1_kernel,
                         cudaFuncAttributeMaxDynamicSharedMemorySize, P1_SMEM);
    cudaFuncSetAttribute((const void*)phase2_kernel,
                         cudaFuncAttributeMaxDynamicSharedMemorySize,
                         N_OBJ * (int)sizeof(uint32_t));

    init_zthr_kernel<<<N_OBJ / 256, 256>>>();
    init_lut_kernel<<<(LUTN + 256 + 255) / 256, 256>>>();
    phase1_kernel<<<296, P1_THREADS, P1_SMEM>>>(q_mu, q_var);
    phase2_kernel<<<N_DIM, 1024, N_OBJ * sizeof(uint32_t)>>>(out);
}

// round 5
// speedup vs baseline: 1.8490x; 1.8490x over previous
#include <cuda_runtime.h>
#include <stdint.h>

#define N_OBJ 16384
#define N_DIM 4096
#define INV_SQRT2 0.70710678118654752440f

// 134 MB scratch: bin index per (dim, object), transposed layout [dim][object].
__device__ uint16_t g_bins[(size_t)N_DIM * N_OBJ];

// thr(j) = 0.05f * float32((j+1)/16384); (j+1)*2^-14 exact, one rounding on *0.05f
__device__ __forceinline__ float thr(int j) {
    return __fmul_rn(0.05f, (float)(j + 1) * 6.103515625e-05f);
}

// ---------------- phase 1: arithmetic bins, transposed tile write ---------
// Block 256 = (32 tx=dim, 8 ty=obj), 8 objs/thread -> tile 32 dims x 64 objs.
#define P1_THREADS 256

__global__ void __launch_bounds__(P1_THREADS) phase1_kernel(
        const float* __restrict__ q_mu, const float* __restrict__ q_var) {
    __shared__ uint16_t s_tile[32 * 66];            // [dim][obj], padded

    const int tid = threadIdx.x, tx = tid & 31, ty = tid >> 5;
    const int dt = blockIdx.x;                       // 0..127  (dim tile)
    const int ot = blockIdx.y;                       // 0..255  (obj tile, 64 objs)
    const int d = dt * 32 + tx;
    const size_t base = (size_t)(ot * 64 + ty) * N_DIM + d;

    float mm[8], vv[8];
    #pragma unroll
    for (int r = 0; r < 8; r++) {
        mm[r] = q_mu[base + (size_t)(r * 8) * N_DIM];
        vv[r] = q_var[base + (size_t)(r * 8) * N_DIM];
    }

    #pragma unroll
    for (int r = 0; r < 8; r++) {
        // p = 0.5*erfc(x), x = (mu/v)/sqrt2.  p <= 0.05 requires x >= 1.6449,
        // so clamping x to >= 1 only remaps values that land in the sentinel
        // region anyway (p(1) = 0.0786 > 0.05).
        float x = __fdividef(mm[r], vv[r]) * INV_SQRT2;
        float xc = fmaxf(x, 1.0f);

        // exp(-x^2) with Dekker-corrected argument
        float h = xc * xc;
        float l = fmaf(xc, xc, -h);
        float e = __expf(-h);
        e = fmaf(-l, e, e);

        // Abramowitz-Stegun 7.1.26 rational, |abs err| <= 1.5e-7
        float den = fmaf(0.3275911f, xc, 1.0f);
        float t = __fdividef(1.0f, den);
        float poly = fmaf(t, 1.061405429f, -1.453152027f);
        poly = fmaf(t, poly, 1.421413741f);
        poly = fmaf(t, poly, -0.284496736f);
        poly = fmaf(t, poly, 0.254829592f);
        float p = 0.5f * t * poly * e;

        uint16_t bin = 0xFFFFu;
        if (p <= 0.05f) {                            // thr(16383) == 0.05f exactly
            int j = (int)ceilf(p * 327680.0f) - 1;   // thresholds uniform in p
            j = min(max(j, 0), N_OBJ - 1);
            while (j > 0 && p <= thr(j - 1)) --j;    // fp fixup, ~0-1 iters
            while (j < N_OBJ - 1 && p > thr(j)) ++j;
            bin = (uint16_t)j;
        }
        s_tile[tx * 66 + (ty + r * 8)] = bin;
    }
    __syncthreads();

    // transposed coalesced store: 32 dims x 64 objs = 1024 u32, 128B/warp rows
    uint32_t* bins32 = reinterpret_cast<uint32_t*>(g_bins);
    #pragma unroll
    for (int q = 0; q < 4; q++) {
        int s = q * 256 + tid;
        int dd = s >> 5, pp = s & 31;
        uint32_t val = *(const uint32_t*)&s_tile[dd * 66 + 2 * pp];
        bins32[(size_t)(dt * 32 + dd) * (N_OBJ / 2) + ot * 32 + pp] = val;
    }
}

// ---------------- phase 2: per-dim histogram + bounded scan (round-3) -----
__global__ __launch_bounds__(1024, 2) void phase2_kernel(float* __restrict__ out) {
    extern __shared__ uint32_t hist[];       // up to 16384 u32 = 64 KB
    __shared__ uint32_t warp_part[32];
    __shared__ uint32_t s_carry, s_C;
    __shared__ uint32_t red_cnt[32];
    __shared__ int      red_min[32];

    const int tid = threadIdx.x, lane = tid & 31, wid = tid >> 5;
    const int d = blockIdx.x;

    const uint4* row = (const uint4*)(g_bins + (size_t)d * N_OBJ);
    uint4 ra = row[tid];
    uint4 rb = row[tid + 1024];
    uint32_t w[8] = {ra.x, ra.y, ra.z, ra.w, rb.x, rb.y, rb.z, rb.w};

    // C = #(non-sentinel)
    uint32_t cnt = 0;
    #pragma unroll
    for (int q = 0; q < 8; q++) {
        cnt += ((w[q] & 0xFFFFu) != 0xFFFFu);
        cnt += ((w[q] >> 16)     != 0xFFFFu);
    }
    #pragma unroll
    for (int o = 16; o > 0; o >>= 1) cnt += __shfl_down_sync(0xffffffffu, cnt, o);
    if (tid == 0) { s_C = 0; s_carry = 0; }
    __syncthreads();
    if (lane == 0 && cnt) atomicAdd(&s_C, cnt);
    __syncthreads();

    const uint32_t C = s_C;
    const int chunks = min(16, (int)((C + 1023u) >> 10));
    if (chunks == 0) { if (tid == 0) out[d] = 0.0f; return; }
    const uint32_t limit = (uint32_t)chunks << 10;

    {   // vectorized zero of hist[0..limit)
        uint4* h4 = (uint4*)hist;
        uint4 z4 = {0u, 0u, 0u, 0u};
        for (int k = tid; k < (int)(limit >> 2); k += 1024) h4[k] = z4;
    }
    __syncthreads();

    uint32_t zc = 0;                          // bin 0 is hot -> warp-aggregate
    #pragma unroll
    for (int q = 0; q < 8; q++) {
        uint32_t b0 = w[q] & 0xFFFFu, b1 = w[q] >> 16;
        if (b0 == 0u) zc++; else if (b0 < limit) atomicAdd(&hist[b0], 1u);
        if (b1 == 0u) zc++; else if (b1 < limit) atomicAdd(&hist[b1], 1u);
    }
    #pragma unroll
    for (int o = 16; o > 0; o >>= 1) zc += __shfl_down_sync(0xffffffffu, zc, o);
    if (lane == 0 && zc) atomicAdd(&hist[0], zc);
    __syncthreads();

    // chunked inclusive scan over [0, limit): reject[j] = cum(j) >= j+1
    uint32_t count = 0;
    int firstj = 0x7fffffff;
    for (int c = 0; c < chunks; ++c) {
        int j = c * 1024 + tid;
        uint32_t x = hist[j];
        #pragma unroll
        for (int o = 1; o < 32; o <<= 1) {
            uint32_t y = __shfl_up_sync(0xffffffffu, x, o);
            if (lane >= o) x += y;
        }
        if (lane == 31) warp_part[wid] = x;
        __syncthreads();
        if (wid == 0) {
            uint32_t ww = warp_part[lane];
            #pragma unroll
            for (int o = 1; o < 32; o <<= 1) {
                uint32_t y = __shfl_up_sync(0xffffffffu, ww, o);
                if (lane >= o) ww += y;
            }
            warp_part[lane] = ww;
        }
        __syncthreads();
        uint32_t incl = x + (wid > 0 ? warp_part[wid - 1] : 0u) + s_carry;
        if (incl >= (uint32_t)(j + 1)) { count++; firstj = min(firstj, j); }
        __syncthreads();
        if (tid == 0) s_carry += warp_part[31];
        __syncthreads();
    }

    #pragma unroll
    for (int o = 16; o > 0; o >>= 1) {
        count += __shfl_down_sync(0xffffffffu, count, o);
        firstj = min(firstj, __shfl_down_sync(0xffffffffu, firstj, o));
    }
    if (lane == 0) { red_cnt[wid] = count; red_min[wid] = firstj; }
    __syncthreads();
    if (wid == 0) {
        uint32_t cc = red_cnt[lane];
        int mm = red_min[lane];
        #pragma unroll
        for (int o = 16; o > 0; o >>= 1) {
            cc += __shfl_down_sync(0xffffffffu, cc, o);
            mm = min(mm, __shfl_down_sync(0xffffffffu, mm, o));
        }
        if (lane == 0) {
            uint32_t imp = cc + ((mm == 0x7fffffff) ? 0u : (uint32_t)mm);
            out[d] = (float)imp;
        }
    }
}

extern "C" void kernel_launch(void* const* d_in, const int* in_sizes, int n_in,
                              void* d_out, int out_size) {
    const float* q_mu  = (const float*)d_in[0];
    const float* q_var = (const float*)d_in[1];
    float* out = (float*)d_out;

    cudaFuncSetAttribute((const void*)phase2_kernel,
                         cudaFuncAttributeMaxDynamicSharedMemorySize,
                         N_OBJ * (int)sizeof(uint32_t));

    dim3 g1(N_DIM / 32, N_OBJ / 64);
    phase1_kernel<<<g1, P1_THREADS>>>(q_mu, q_var);
    phase2_kernel<<<N_DIM, 1024, N_OBJ * sizeof(uint32_t)>>>(out);
}